// round 14
// baseline (speedup 1.0000x reference)
#include <cuda_runtime.h>
#include <cuda_fp16.h>
#include <cuda_bf16.h>
#include <math.h>
#include <stdint.h>

// Problem constants
#define DIMM   768
#define NHEAD  12
#define HDIM   64
#define BATCH  2
#define GRID_H 48
#define NSEQ   2304          // 48*48
#define BHN    24            // BATCH*NHEAD
#define MROWS  4608          // BATCH*NSEQ
#define SCALE  0.125f        // 64^-0.5
#define LOG2E  1.44269504088896f

// ---------------- device scratch (static: no cudaMalloc allowed) ----------------
__device__ float  g_q [BHN * NSEQ * HDIM];      // [bh][n][c], unscaled fp32
__device__ __half g_kh[BHN * NSEQ * HDIM];      // [bh][n][c] fp16
__device__ __half g_vt[BHN * HDIM * NSEQ];      // [bh][c][n] fp16 (transposed)
__device__ float  g_relh[BHN * NSEQ * GRID_H];  // [bh][q][kh] (pre-scaled by log2e)
__device__ float  g_relw[BHN * NSEQ * GRID_H];  // [bh][q][kw] (pre-scaled by log2e)
__device__ float  g_ao[MROWS * DIMM];           // attention output (b,n,dim)

// ---------------- helpers ----------------
__device__ __forceinline__ uint32_t packh2(float a, float b) {
    __half2 h = __floats2half2_rn(a, b);
    return *(uint32_t*)&h;
}
__device__ __forceinline__ uint32_t ex2h2(uint32_t x) {
    uint32_t r;
    asm("ex2.approx.f16x2 %0, %1;" : "=r"(r) : "r"(x));
    return r;
}

// D(16x8,f32) += A(16x16,f16,row) * B(16x8,f16,col)
__device__ __forceinline__ void mma_f16(float* d, const uint32_t* a,
                                        uint32_t b0, uint32_t b1) {
    asm volatile(
        "mma.sync.aligned.m16n8k16.row.col.f32.f16.f16.f32 "
        "{%0,%1,%2,%3}, {%4,%5,%6,%7}, {%8,%9}, {%0,%1,%2,%3};"
        : "+f"(d[0]), "+f"(d[1]), "+f"(d[2]), "+f"(d[3])
        : "r"(a[0]), "r"(a[1]), "r"(a[2]), "r"(a[3]), "r"(b0), "r"(b1));
}

__device__ __forceinline__ void cp_async16(void* smem_dst, const void* gmem_src) {
    uint32_t s = (uint32_t)__cvta_generic_to_shared(smem_dst);
    asm volatile("cp.async.cg.shared.global [%0], [%1], 16;\n" :: "r"(s), "l"(gmem_src));
}
__device__ __forceinline__ void cp_commit() { asm volatile("cp.async.commit_group;\n"); }
#define CP_WAIT_GROUP(n) asm volatile("cp.async.wait_group %0;\n" :: "n"(n))

// =================================================================
// fp16 tensor-core GEMM NT, cp.async 3-stage pipeline (R11 proven).
// =================================================================
#define GPAD 24

template<int MODE>
__global__ __launch_bounds__(256, 2) void gemm_tc(const float* __restrict__ Aext,
                                                  const float* __restrict__ B,
                                                  const float* __restrict__ bias,
                                                  float* __restrict__ Cout,
                                                  int Ncol, int K)
{
    __shared__ float As[3][128][GPAD];
    __shared__ float Bs[3][128][GPAD];
    const float* A = (MODE == 0) ? Aext : (const float*)g_ao;

    const int m0 = blockIdx.y * 128;
    const int n0 = blockIdx.x * 128;
    const int tid = threadIdx.x;
    const int lane = tid & 31;
    const int wid = tid >> 5;
    const int wm = (wid & 1) * 64;
    const int wn = (wid >> 1) * 32;
    const int gr = lane >> 2;
    const int gc = lane & 3;
    const int sr = tid >> 2;
    const int sc = (tid & 3) << 2;

    float acc[4][4][4];
#pragma unroll
    for (int mi = 0; mi < 4; mi++)
#pragma unroll
        for (int ni = 0; ni < 4; ni++)
#pragma unroll
            for (int j = 0; j < 4; j++) acc[mi][ni][j] = 0.f;

    auto issue = [&](int k0, int pb) {
        cp_async16(&As[pb][sr][sc],      A + (size_t)(m0 + sr) * K + k0 + sc);
        cp_async16(&As[pb][sr + 64][sc], A + (size_t)(m0 + sr + 64) * K + k0 + sc);
        cp_async16(&Bs[pb][sr][sc],      B + (size_t)(n0 + sr) * K + k0 + sc);
        cp_async16(&Bs[pb][sr + 64][sc], B + (size_t)(n0 + sr + 64) * K + k0 + sc);
        cp_commit();
    };

    issue(0, 0);
    issue(16, 1);

    const int nk = K / 16;
    int p = 0;
    for (int kt = 0; kt < nk; kt++) {
        CP_WAIT_GROUP(1);
        __syncthreads();
        if (kt + 2 < nk) issue((kt + 2) * 16, (p + 2 >= 3) ? p - 1 : p + 2);

        uint32_t af[4][4], bf[4][2];
#pragma unroll
        for (int mi = 0; mi < 4; mi++) {
            const float* ap0 = &As[p][wm + mi * 16 + gr][2 * gc];
            const float* ap1 = ap0 + 8 * GPAD;
            float2 x0 = *(const float2*)ap0;
            float2 x1 = *(const float2*)ap1;
            float2 x2 = *(const float2*)(ap0 + 8);
            float2 x3 = *(const float2*)(ap1 + 8);
            af[mi][0] = packh2(x0.x, x0.y);
            af[mi][1] = packh2(x1.x, x1.y);
            af[mi][2] = packh2(x2.x, x2.y);
            af[mi][3] = packh2(x3.x, x3.y);
        }
#pragma unroll
        for (int ni = 0; ni < 4; ni++) {
            const float* bp = &Bs[p][wn + ni * 8 + gr][2 * gc];
            float2 y0 = *(const float2*)bp;
            float2 y1 = *(const float2*)(bp + 8);
            bf[ni][0] = packh2(y0.x, y0.y);
            bf[ni][1] = packh2(y1.x, y1.y);
        }
#pragma unroll
        for (int mi = 0; mi < 4; mi++)
#pragma unroll
            for (int ni = 0; ni < 4; ni++)
                mma_f16(acc[mi][ni], af[mi], bf[ni][0], bf[ni][1]);

        p = (p + 1 >= 3) ? 0 : p + 1;
    }

    // ---- epilogue
#pragma unroll
    for (int ni = 0; ni < 4; ni++) {
        const int nb = n0 + wn + ni * 8 + 2 * gc;
        const float bbx = bias[nb], bby = bias[nb + 1];
        if (MODE == 0) {
            const int part = nb / DIMM;
            const int hh = (nb % DIMM) / HDIM;
            const int cb = nb % HDIM;
#pragma unroll
            for (int mi = 0; mi < 4; mi++) {
                int m = m0 + wm + mi * 16 + gr;
                int b = m / NSEQ, nn = m % NSEQ;
                int bh = b * NHEAD + hh;
                float v0 = acc[mi][ni][0] + bbx, v1 = acc[mi][ni][1] + bby;
                float v2 = acc[mi][ni][2] + bbx, v3 = acc[mi][ni][3] + bby;
                if (part == 0) {
                    float* d0 = g_q + (size_t)(bh * NSEQ + nn) * HDIM + cb;
                    *(float2*)d0 = make_float2(v0, v1);
                    *(float2*)(d0 + 8 * HDIM) = make_float2(v2, v3);
                } else if (part == 1) {
                    __half* d0 = g_kh + (size_t)(bh * NSEQ + nn) * HDIM + cb;
                    *(__half2*)d0 = __floats2half2_rn(v0, v1);
                    *(__half2*)(d0 + 8 * HDIM) = __floats2half2_rn(v2, v3);
                } else {
                    __half* base = g_vt + (size_t)bh * HDIM * NSEQ;
                    base[(size_t)cb * NSEQ + nn] = __float2half_rn(v0);
                    base[(size_t)(cb + 1) * NSEQ + nn] = __float2half_rn(v1);
                    base[(size_t)cb * NSEQ + nn + 8] = __float2half_rn(v2);
                    base[(size_t)(cb + 1) * NSEQ + nn + 8] = __float2half_rn(v3);
                }
            }
        } else {
#pragma unroll
            for (int mi = 0; mi < 4; mi++) {
                int m = m0 + wm + mi * 16 + gr;
                *(float2*)(Cout + (size_t)m * Ncol + nb) =
                    make_float2(acc[mi][ni][0] + bbx, acc[mi][ni][1] + bby);
                *(float2*)(Cout + (size_t)(m + 8) * Ncol + nb) =
                    make_float2(acc[mi][ni][2] + bbx, acc[mi][ni][3] + bby);
            }
        }
    }
}

// =================================================================
// rel bias tables — outputs pre-multiplied by log2(e)
// =================================================================
#define REL_SMEM ((3072 + 3072 + 6080) * 4)

__global__ __launch_bounds__(256) void rel_kernel(const float* __restrict__ rph,
                                                  const float* __restrict__ rpw)
{
    extern __shared__ float sm[];
    float* qs = sm;            // [48][64]
    float* rh = sm + 3072;     // [48][64]
    float* rw = sm + 6144;     // [95][64]

    const int qh = blockIdx.x;
    const int bh = blockIdx.y;
    const int tid = threadIdx.x;

    const float4* qsrc = (const float4*)(g_q + (size_t)(bh * NSEQ + qh * GRID_H) * HDIM);
#pragma unroll
    for (int i = 0; i < 3; i++) ((float4*)qs)[tid + i * 256] = qsrc[tid + i * 256];

    for (int i = tid; i < 768; i += 256) {
        int kh = i >> 4, cc = i & 15;
        ((float4*)rh)[i] = ((const float4*)(rph + (size_t)(qh - kh + 47) * HDIM))[cc];
    }
    for (int i = tid; i < 1520; i += 256) ((float4*)rw)[i] = ((const float4*)rpw)[i];
    __syncthreads();

    for (int idx = tid; idx < 2304; idx += 256) {
        int qw = idx / GRID_H;
        int kk = idx - qw * GRID_H;
        const float4* qp = (const float4*)(qs + qw * HDIM);
        const float4* hp = (const float4*)(rh + kk * HDIM);
        const float4* wp = (const float4*)(rw + (qw - kk + 47) * HDIM);
        float sh = 0.f, sw2 = 0.f;
#pragma unroll
        for (int c = 0; c < 16; c++) {
            float4 a = qp[c], hb = hp[c], wb = wp[c];
            sh  += a.x * hb.x + a.y * hb.y + a.z * hb.z + a.w * hb.w;
            sw2 += a.x * wb.x + a.y * wb.y + a.z * wb.z + a.w * wb.w;
        }
        size_t base = ((size_t)bh * NSEQ + (size_t)qh * GRID_H + qw) * GRID_H + kk;
        g_relh[base] = sh * LOG2E;
        g_relw[base] = sw2 * LOG2E;
    }
}

// =================================================================
// Flash attention: 64-q tile, 4 warps, 128 threads, 2-slot K/V ring
// -> ~49KB smem -> 2 independent CTAs/SM (decoupled barrier domains).
// fp16 mma, f16x2 exp, l-via-ones-mma, paired bf16x2 rw bias loads.
// =================================================================
#define KHS 72                 // fp16 row stride (36 u32 ≡ 4 mod 32)
#define KHW 36                 // stride in u32
#define RLS 52
#define SLOT_H (64 * KHS)      // fp16 elems per slot
#define FLASH_SMEM (4 * SLOT_H * 2 + 2 * 64 * RLS * 2)   // 50176 B
#define ONES_H2 0x3C003C00u    // half2(1.0, 1.0)

__global__ __launch_bounds__(128, 2) void flash_tc()
{
    extern __shared__ char smraw[];
    __half* Kb = (__half*)smraw;                          // [2][64][72]
    __half* Vb = Kb + 2 * SLOT_H;                         // [2][64][72] (V^T)
    __nv_bfloat16* RHb = (__nv_bfloat16*)(Vb + 2 * SLOT_H);   // [64][52]
    __nv_bfloat16* RWb = RHb + 64 * RLS;                  // [64][52]

    const int bh = blockIdx.y;
    const int q0 = blockIdx.x * 64;
    const int tid = threadIdx.x;
    const int lane = tid & 31;
    const int wid = tid >> 5;           // 0..3
    const int wrow = wid * 16;
    const int gr = lane >> 2;
    const int gc = lane & 3;

    const float* qg = g_q + (size_t)bh * NSEQ * HDIM;
    const __half* kg = g_kh + (size_t)bh * NSEQ * HDIM;
    const __half* vtg = g_vt + (size_t)bh * HDIM * NSEQ;

    const int ldrow = tid >> 1;          // 0..63
    const int ldc0 = (tid & 1) * 32;     // fp16 half-row base

    auto issue = [&](int tile) {
        const __half* ksrc = kg + (size_t)(tile * 64 + ldrow) * HDIM + ldc0;
        const __half* vsrc = vtg + (size_t)ldrow * NSEQ + tile * 64 + ldc0;
        __half* kd = Kb + (tile & 1) * SLOT_H + ldrow * KHS + ldc0;
        __half* vd = Vb + (tile & 1) * SLOT_H + ldrow * KHS + ldc0;
#pragma unroll
        for (int i = 0; i < 4; i++) {
            cp_async16(kd + i * 8, ksrc + i * 8);
            cp_async16(vd + i * 8, vsrc + i * 8);
        }
        cp_commit();
    };

    // ---- Q fragments (fp16, scaled by SCALE*log2e)
    uint32_t qa[4][4];
    {
        const float qsc = SCALE * LOG2E;
        const float* qr0 = qg + (size_t)(q0 + wrow + gr) * HDIM;
        const float* qr1 = qr0 + 8 * HDIM;
#pragma unroll
        for (int ks = 0; ks < 4; ks++) {
            int c = ks * 16 + 2 * gc;
            qa[ks][0] = packh2(qr0[c] * qsc, qr0[c + 1] * qsc);
            qa[ks][1] = packh2(qr1[c] * qsc, qr1[c + 1] * qsc);
            qa[ks][2] = packh2(qr0[c + 8] * qsc, qr0[c + 9] * qsc);
            qa[ks][3] = packh2(qr1[c + 8] * qsc, qr1[c + 9] * qsc);
        }
    }

    // ---- rel bias slices -> bf16 SMEM [64][48] (stride 52)
    {
        const float4* srcH = (const float4*)(g_relh + ((size_t)bh * NSEQ + q0) * GRID_H);
        const float4* srcW = (const float4*)(g_relw + ((size_t)bh * NSEQ + q0) * GRID_H);
        for (int i = tid; i < 768; i += 128) {   // 64 rows * 12 float4/row
            int r = i / 12, c4 = i % 12;
            float4 vh = srcH[i], vw = srcW[i];
            __nv_bfloat162* dh = (__nv_bfloat162*)(RHb + r * RLS + c4 * 4);
            __nv_bfloat162* dw = (__nv_bfloat162*)(RWb + r * RLS + c4 * 4);
            dh[0] = __floats2bfloat162_rn(vh.x, vh.y);
            dh[1] = __floats2bfloat162_rn(vh.z, vh.w);
            dw[0] = __floats2bfloat162_rn(vw.x, vw.y);
            dw[1] = __floats2bfloat162_rn(vw.z, vw.w);
        }
    }

    // S-tile: s = Q @ K(tile)^T
    float s[8][4];
    auto computeS = [&](int tile) {
        const uint32_t* Kp = (const uint32_t*)(Kb + (tile & 1) * SLOT_H);
#pragma unroll
        for (int nt = 0; nt < 8; nt++) {
            s[nt][0] = s[nt][1] = s[nt][2] = s[nt][3] = 0.f;
            const uint32_t* kb = Kp + (nt * 8 + gr) * KHW;
#pragma unroll
            for (int ks = 0; ks < 4; ks++)
                mma_f16(s[nt], qa[ks], kb[ks * 8 + gc], kb[ks * 8 + gc + 4]);
        }
    };

    issue(0); issue(1);
    CP_WAIT_GROUP(0);
    __syncthreads();
    computeS(0);

    float o[8][4];
    float lacc[4] = {0.f, 0.f, 0.f, 0.f};
#pragma unroll
    for (int nt = 0; nt < 8; nt++)
#pragma unroll
        for (int j = 0; j < 4; j++) o[nt][j] = 0.f;

    const int NIT = NSEQ / 64;   // 36
    for (int it = 0; it < NIT; it++) {
        const int k0 = it * 64;

        // ---- s += bias; rw loaded as bf16x2 pairs (kw0 always even, no wrap
        // within a pair), rh shared between the pair (kh1 == kh0).
        {
            const __nv_bfloat16* rh0 = RHb + (wrow + gr) * RLS;
            const __nv_bfloat16* rw0 = RWb + (wrow + gr) * RLS;
            const __nv_bfloat16* rh1 = rh0 + 8 * RLS;
            const __nv_bfloat16* rw1 = rw0 + 8 * RLS;
            int c0 = k0 + 2 * gc;
            int kh0 = c0 / GRID_H;
            int kw0 = c0 - kh0 * GRID_H;     // even
#pragma unroll
            for (int nt = 0; nt < 8; nt++) {
                float rhv0 = __bfloat162float(rh0[kh0]);
                float rhv1 = __bfloat162float(rh1[kh0]);
                float2 rwv0 = __bfloat1622float2(*(const __nv_bfloat162*)(rw0 + kw0));
                float2 rwv1 = __bfloat1622float2(*(const __nv_bfloat162*)(rw1 + kw0));
                s[nt][0] += rhv0 + rwv0.x;
                s[nt][1] += rhv0 + rwv0.y;
                s[nt][2] += rhv1 + rwv1.x;
                s[nt][3] += rhv1 + rwv1.y;
                kw0 += 8;
                if (kw0 >= GRID_H) { kw0 -= GRID_H; kh0++; }
            }
        }

        // ---- P = exp2(s) in fp16 pairs
        uint32_t pf[4][4];
#pragma unroll
        for (int ks = 0; ks < 4; ks++) {
            pf[ks][0] = ex2h2(packh2(s[2 * ks][0], s[2 * ks][1]));
            pf[ks][1] = ex2h2(packh2(s[2 * ks][2], s[2 * ks][3]));
            pf[ks][2] = ex2h2(packh2(s[2 * ks + 1][0], s[2 * ks + 1][1]));
            pf[ks][3] = ex2h2(packh2(s[2 * ks + 1][2], s[2 * ks + 1][3]));
        }

        // ---- l row-sums via ones-mma
#pragma unroll
        for (int ks = 0; ks < 4; ks++)
            mma_f16(lacc, pf[ks], ONES_H2, ONES_H2);

        // ---- O += P @ V (slot it&1)
        {
            const uint32_t* Vp = (const uint32_t*)(Vb + (it & 1) * SLOT_H);
#pragma unroll
            for (int nt = 0; nt < 8; nt++) {
                const uint32_t* vb = Vp + (nt * 8 + gr) * KHW;
#pragma unroll
                for (int ks = 0; ks < 4; ks++)
                    mma_f16(o[nt], pf[ks], vb[ks * 8 + gc], vb[ks * 8 + gc + 4]);
            }
        }

        // ---- ring tail: all warps done with slot it&1 -> refill it, then
        // ensure tile it+1 resident and pipeline its S.
        __syncthreads();
        if (it + 2 < NIT) {
            issue(it + 2);
            CP_WAIT_GROUP(1);
        } else {
            CP_WAIT_GROUP(0);
        }
        if (it + 1 < NIT) computeS(it + 1);
    }

    // ---- epilogue: l complete per-lane (ones-mma); write g_ao
    const int b = bh / NHEAD, hh = bh % NHEAD;
    const float inv0 = 1.f / lacc[0], inv1 = 1.f / lacc[2];
    float* d0 = g_ao + (size_t)(b * NSEQ + q0 + wrow + gr) * DIMM + hh * HDIM + 2 * gc;
    float* d1 = d0 + (size_t)8 * DIMM;
#pragma unroll
    for (int nt = 0; nt < 8; nt++) {
        *(float2*)(d0 + nt * 8) = make_float2(o[nt][0] * inv0, o[nt][1] * inv0);
        *(float2*)(d1 + nt * 8) = make_float2(o[nt][2] * inv1, o[nt][3] * inv1);
    }
}

// =================================================================
extern "C" void kernel_launch(void* const* d_in, const int* in_sizes, int n_in,
                              void* d_out, int out_size)
{
    const float* x     = (const float*)d_in[0];
    const float* rph   = (const float*)d_in[1];
    const float* rpw   = (const float*)d_in[2];
    const float* qkvw  = (const float*)d_in[3];
    const float* qkvb  = (const float*)d_in[4];
    const float* projw = (const float*)d_in[5];
    const float* projb = (const float*)d_in[6];
    float* out = (float*)d_out;

    cudaFuncSetAttribute(flash_tc,   cudaFuncAttributeMaxDynamicSharedMemorySize, FLASH_SMEM);
    cudaFuncSetAttribute(rel_kernel, cudaFuncAttributeMaxDynamicSharedMemorySize, REL_SMEM);

    // 1) QKV projection + head split (fp16 mma, 3-stage pipeline)
    gemm_tc<0><<<dim3(2304 / 128, MROWS / 128), dim3(256)>>>(x, qkvw, qkvb, nullptr, 2304, DIMM);
    // 2) rel-pos bias tables (log2e-scaled)
    rel_kernel<<<dim3(GRID_H, BHN), dim3(256), REL_SMEM>>>(rph, rpw);
    // 3) fused flash attention (64-q tiles, 2 CTAs/SM, paired bias loads)
    flash_tc<<<dim3(NSEQ / 64, BHN), dim3(128), FLASH_SMEM>>>();
    // 4) output projection (fp16 mma, 3-stage pipeline)
    gemm_tc<1><<<dim3(DIMM / 128, MROWS / 128), dim3(256)>>>(nullptr, projw, projb, out, DIMM, DIMM);
}

// round 15
// speedup vs baseline: 1.0793x; 1.0793x over previous
#include <cuda_runtime.h>
#include <cuda_fp16.h>
#include <cuda_bf16.h>
#include <math.h>
#include <stdint.h>

// Problem constants
#define DIMM   768
#define NHEAD  12
#define HDIM   64
#define BATCH  2
#define GRID_H 48
#define NSEQ   2304          // 48*48
#define BHN    24            // BATCH*NHEAD
#define MROWS  4608          // BATCH*NSEQ
#define SCALE  0.125f        // 64^-0.5
#define LOG2E  1.44269504088896f

// ---------------- device scratch (static: no cudaMalloc allowed) ----------------
__device__ float  g_q [BHN * NSEQ * HDIM];      // [bh][n][c], unscaled fp32
__device__ __half g_kh[BHN * NSEQ * HDIM];      // [bh][n][c] fp16
__device__ __half g_vt[BHN * HDIM * NSEQ];      // [bh][c][n] fp16 (transposed)
__device__ float  g_relh[BHN * NSEQ * GRID_H];  // [bh][q][kh] (pre-scaled by log2e)
__device__ float  g_relw[BHN * NSEQ * GRID_H];  // [bh][q][kw] (pre-scaled by log2e)
__device__ float  g_ao[MROWS * DIMM];           // attention output (b,n,dim)

// ---------------- helpers ----------------
__device__ __forceinline__ uint32_t packh2(float a, float b) {
    __half2 h = __floats2half2_rn(a, b);
    return *(uint32_t*)&h;
}
__device__ __forceinline__ uint32_t ex2h2(uint32_t x) {
    uint32_t r;
    asm("ex2.approx.f16x2 %0, %1;" : "=r"(r) : "r"(x));
    return r;
}

// D(16x8,f32) += A(16x16,f16,row) * B(16x8,f16,col)
__device__ __forceinline__ void mma_f16(float* d, const uint32_t* a,
                                        uint32_t b0, uint32_t b1) {
    asm volatile(
        "mma.sync.aligned.m16n8k16.row.col.f32.f16.f16.f32 "
        "{%0,%1,%2,%3}, {%4,%5,%6,%7}, {%8,%9}, {%0,%1,%2,%3};"
        : "+f"(d[0]), "+f"(d[1]), "+f"(d[2]), "+f"(d[3])
        : "r"(a[0]), "r"(a[1]), "r"(a[2]), "r"(a[3]), "r"(b0), "r"(b1));
}

__device__ __forceinline__ void cp_async16(void* smem_dst, const void* gmem_src) {
    uint32_t s = (uint32_t)__cvta_generic_to_shared(smem_dst);
    asm volatile("cp.async.cg.shared.global [%0], [%1], 16;\n" :: "r"(s), "l"(gmem_src));
}
__device__ __forceinline__ void cp_commit() { asm volatile("cp.async.commit_group;\n"); }
#define CP_WAIT_GROUP(n) asm volatile("cp.async.wait_group %0;\n" :: "n"(n))

// =================================================================
// fp16 tensor-core GEMM NT, cp.async 3-stage pipeline (R11 proven).
// =================================================================
#define GPAD 24

template<int MODE>
__global__ __launch_bounds__(256, 2) void gemm_tc(const float* __restrict__ Aext,
                                                  const float* __restrict__ B,
                                                  const float* __restrict__ bias,
                                                  float* __restrict__ Cout,
                                                  int Ncol, int K)
{
    __shared__ float As[3][128][GPAD];
    __shared__ float Bs[3][128][GPAD];
    const float* A = (MODE == 0) ? Aext : (const float*)g_ao;

    const int m0 = blockIdx.y * 128;
    const int n0 = blockIdx.x * 128;
    const int tid = threadIdx.x;
    const int lane = tid & 31;
    const int wid = tid >> 5;
    const int wm = (wid & 1) * 64;
    const int wn = (wid >> 1) * 32;
    const int gr = lane >> 2;
    const int gc = lane & 3;
    const int sr = tid >> 2;
    const int sc = (tid & 3) << 2;

    float acc[4][4][4];
#pragma unroll
    for (int mi = 0; mi < 4; mi++)
#pragma unroll
        for (int ni = 0; ni < 4; ni++)
#pragma unroll
            for (int j = 0; j < 4; j++) acc[mi][ni][j] = 0.f;

    auto issue = [&](int k0, int pb) {
        cp_async16(&As[pb][sr][sc],      A + (size_t)(m0 + sr) * K + k0 + sc);
        cp_async16(&As[pb][sr + 64][sc], A + (size_t)(m0 + sr + 64) * K + k0 + sc);
        cp_async16(&Bs[pb][sr][sc],      B + (size_t)(n0 + sr) * K + k0 + sc);
        cp_async16(&Bs[pb][sr + 64][sc], B + (size_t)(n0 + sr + 64) * K + k0 + sc);
        cp_commit();
    };

    issue(0, 0);
    issue(16, 1);

    const int nk = K / 16;
    int p = 0;
    for (int kt = 0; kt < nk; kt++) {
        CP_WAIT_GROUP(1);
        __syncthreads();
        if (kt + 2 < nk) issue((kt + 2) * 16, (p + 2 >= 3) ? p - 1 : p + 2);

        uint32_t af[4][4], bf[4][2];
#pragma unroll
        for (int mi = 0; mi < 4; mi++) {
            const float* ap0 = &As[p][wm + mi * 16 + gr][2 * gc];
            const float* ap1 = ap0 + 8 * GPAD;
            float2 x0 = *(const float2*)ap0;
            float2 x1 = *(const float2*)ap1;
            float2 x2 = *(const float2*)(ap0 + 8);
            float2 x3 = *(const float2*)(ap1 + 8);
            af[mi][0] = packh2(x0.x, x0.y);
            af[mi][1] = packh2(x1.x, x1.y);
            af[mi][2] = packh2(x2.x, x2.y);
            af[mi][3] = packh2(x3.x, x3.y);
        }
#pragma unroll
        for (int ni = 0; ni < 4; ni++) {
            const float* bp = &Bs[p][wn + ni * 8 + gr][2 * gc];
            float2 y0 = *(const float2*)bp;
            float2 y1 = *(const float2*)(bp + 8);
            bf[ni][0] = packh2(y0.x, y0.y);
            bf[ni][1] = packh2(y1.x, y1.y);
        }
#pragma unroll
        for (int mi = 0; mi < 4; mi++)
#pragma unroll
            for (int ni = 0; ni < 4; ni++)
                mma_f16(acc[mi][ni], af[mi], bf[ni][0], bf[ni][1]);

        p = (p + 1 >= 3) ? 0 : p + 1;
    }

    // ---- epilogue
#pragma unroll
    for (int ni = 0; ni < 4; ni++) {
        const int nb = n0 + wn + ni * 8 + 2 * gc;
        const float bbx = bias[nb], bby = bias[nb + 1];
        if (MODE == 0) {
            const int part = nb / DIMM;
            const int hh = (nb % DIMM) / HDIM;
            const int cb = nb % HDIM;
#pragma unroll
            for (int mi = 0; mi < 4; mi++) {
                int m = m0 + wm + mi * 16 + gr;
                int b = m / NSEQ, nn = m % NSEQ;
                int bh = b * NHEAD + hh;
                float v0 = acc[mi][ni][0] + bbx, v1 = acc[mi][ni][1] + bby;
                float v2 = acc[mi][ni][2] + bbx, v3 = acc[mi][ni][3] + bby;
                if (part == 0) {
                    float* d0 = g_q + (size_t)(bh * NSEQ + nn) * HDIM + cb;
                    *(float2*)d0 = make_float2(v0, v1);
                    *(float2*)(d0 + 8 * HDIM) = make_float2(v2, v3);
                } else if (part == 1) {
                    __half* d0 = g_kh + (size_t)(bh * NSEQ + nn) * HDIM + cb;
                    *(__half2*)d0 = __floats2half2_rn(v0, v1);
                    *(__half2*)(d0 + 8 * HDIM) = __floats2half2_rn(v2, v3);
                } else {
                    __half* base = g_vt + (size_t)bh * HDIM * NSEQ;
                    base[(size_t)cb * NSEQ + nn] = __float2half_rn(v0);
                    base[(size_t)(cb + 1) * NSEQ + nn] = __float2half_rn(v1);
                    base[(size_t)cb * NSEQ + nn + 8] = __float2half_rn(v2);
                    base[(size_t)(cb + 1) * NSEQ + nn + 8] = __float2half_rn(v3);
                }
            }
        } else {
#pragma unroll
            for (int mi = 0; mi < 4; mi++) {
                int m = m0 + wm + mi * 16 + gr;
                *(float2*)(Cout + (size_t)m * Ncol + nb) =
                    make_float2(acc[mi][ni][0] + bbx, acc[mi][ni][1] + bby);
                *(float2*)(Cout + (size_t)(m + 8) * Ncol + nb) =
                    make_float2(acc[mi][ni][2] + bbx, acc[mi][ni][3] + bby);
            }
        }
    }
}

// =================================================================
// rel bias tables — outputs pre-multiplied by log2(e)
// =================================================================
#define REL_SMEM ((3072 + 3072 + 6080) * 4)

__global__ __launch_bounds__(256) void rel_kernel(const float* __restrict__ rph,
                                                  const float* __restrict__ rpw)
{
    extern __shared__ float sm[];
    float* qs = sm;            // [48][64]
    float* rh = sm + 3072;     // [48][64]
    float* rw = sm + 6144;     // [95][64]

    const int qh = blockIdx.x;
    const int bh = blockIdx.y;
    const int tid = threadIdx.x;

    const float4* qsrc = (const float4*)(g_q + (size_t)(bh * NSEQ + qh * GRID_H) * HDIM);
#pragma unroll
    for (int i = 0; i < 3; i++) ((float4*)qs)[tid + i * 256] = qsrc[tid + i * 256];

    for (int i = tid; i < 768; i += 256) {
        int kh = i >> 4, cc = i & 15;
        ((float4*)rh)[i] = ((const float4*)(rph + (size_t)(qh - kh + 47) * HDIM))[cc];
    }
    for (int i = tid; i < 1520; i += 256) ((float4*)rw)[i] = ((const float4*)rpw)[i];
    __syncthreads();

    for (int idx = tid; idx < 2304; idx += 256) {
        int qw = idx / GRID_H;
        int kk = idx - qw * GRID_H;
        const float4* qp = (const float4*)(qs + qw * HDIM);
        const float4* hp = (const float4*)(rh + kk * HDIM);
        const float4* wp = (const float4*)(rw + (qw - kk + 47) * HDIM);
        float sh = 0.f, sw2 = 0.f;
#pragma unroll
        for (int c = 0; c < 16; c++) {
            float4 a = qp[c], hb = hp[c], wb = wp[c];
            sh  += a.x * hb.x + a.y * hb.y + a.z * hb.z + a.w * hb.w;
            sw2 += a.x * wb.x + a.y * wb.y + a.z * wb.z + a.w * wb.w;
        }
        size_t base = ((size_t)bh * NSEQ + (size_t)qh * GRID_H + qw) * GRID_H + kk;
        g_relh[base] = sh * LOG2E;
        g_relw[base] = sw2 * LOG2E;
    }
}

// =================================================================
// Flash attention (R13 base): fp16 mma, f16x2 exp, l-via-ones-mma,
// 128-q tile, 8 warps, cp.async 4-slot fp16 K/V ring — now with TWO
// 64-key tiles per barrier region (18 sync/wait pairs, not 36).
// =================================================================
#define KHS 72                 // fp16 row stride (36 u32 ≡ 4 mod 32)
#define KHW 36                 // stride in u32
#define RLS 52
#define SLOT_H (64 * KHS)      // fp16 elems per slot
#define FLASH_SMEM (8 * SLOT_H * 2 + 2 * 128 * RLS * 2)
#define ONES_H2 0x3C003C00u    // half2(1.0, 1.0)

__global__ __launch_bounds__(256, 2) void flash_tc()
{
    extern __shared__ char smraw[];
    __half* Kb = (__half*)smraw;                          // [4][64][72]
    __half* Vb = Kb + 4 * SLOT_H;                         // [4][64][72] (V^T)
    __nv_bfloat16* RHb = (__nv_bfloat16*)(Vb + 4 * SLOT_H);
    __nv_bfloat16* RWb = RHb + 128 * RLS;

    const int bh = blockIdx.y;
    const int q0 = blockIdx.x * 128;
    const int tid = threadIdx.x;
    const int lane = tid & 31;
    const int wid = tid >> 5;
    const int wrow = wid * 16;
    const int gr = lane >> 2;
    const int gc = lane & 3;

    const float* qg = g_q + (size_t)bh * NSEQ * HDIM;
    const __half* kg = g_kh + (size_t)bh * NSEQ * HDIM;
    const __half* vtg = g_vt + (size_t)bh * HDIM * NSEQ;

    const int ldrow = tid >> 2;          // 0..63
    const int ldc0 = (tid & 3) * 16;     // fp16 col slice base

    // issue one tile's K/V (NO commit — caller groups tiles)
    auto issue_nc = [&](int tile) {
        const __half* ksrc = kg + (size_t)(tile * 64 + ldrow) * HDIM + ldc0;
        const __half* vsrc = vtg + (size_t)ldrow * NSEQ + tile * 64 + ldc0;
        __half* kd = Kb + (tile & 3) * SLOT_H + ldrow * KHS + ldc0;
        __half* vd = Vb + (tile & 3) * SLOT_H + ldrow * KHS + ldc0;
        cp_async16(kd, ksrc);
        cp_async16(kd + 8, ksrc + 8);
        cp_async16(vd, vsrc);
        cp_async16(vd + 8, vsrc + 8);
    };

    // ---- Q fragments (fp16, scaled by SCALE*log2e)
    uint32_t qa[4][4];
    {
        const float qsc = SCALE * LOG2E;
        const float* qr0 = qg + (size_t)(q0 + wrow + gr) * HDIM;
        const float* qr1 = qr0 + 8 * HDIM;
#pragma unroll
        for (int ks = 0; ks < 4; ks++) {
            int c = ks * 16 + 2 * gc;
            qa[ks][0] = packh2(qr0[c] * qsc, qr0[c + 1] * qsc);
            qa[ks][1] = packh2(qr1[c] * qsc, qr1[c + 1] * qsc);
            qa[ks][2] = packh2(qr0[c + 8] * qsc, qr0[c + 9] * qsc);
            qa[ks][3] = packh2(qr1[c + 8] * qsc, qr1[c + 9] * qsc);
        }
    }

    // ---- rel bias slices -> bf16 SMEM [128][48] (stride 52)
    {
        const float4* srcH = (const float4*)(g_relh + ((size_t)bh * NSEQ + q0) * GRID_H);
        const float4* srcW = (const float4*)(g_relw + ((size_t)bh * NSEQ + q0) * GRID_H);
        for (int i = tid; i < 1536; i += 256) {
            int r = i / 12, c4 = i % 12;
            float4 vh = srcH[i], vw = srcW[i];
            __nv_bfloat162* dh = (__nv_bfloat162*)(RHb + r * RLS + c4 * 4);
            __nv_bfloat162* dw = (__nv_bfloat162*)(RWb + r * RLS + c4 * 4);
            dh[0] = __floats2bfloat162_rn(vh.x, vh.y);
            dh[1] = __floats2bfloat162_rn(vh.z, vh.w);
            dw[0] = __floats2bfloat162_rn(vw.x, vw.y);
            dw[1] = __floats2bfloat162_rn(vw.z, vw.w);
        }
    }

    // S-tile: s = Q @ K(tile)^T
    float s[8][4];
    auto computeS = [&](int tile) {
        const uint32_t* Kp = (const uint32_t*)(Kb + (tile & 3) * SLOT_H);
#pragma unroll
        for (int nt = 0; nt < 8; nt++) {
            s[nt][0] = s[nt][1] = s[nt][2] = s[nt][3] = 0.f;
            const uint32_t* kb = Kp + (nt * 8 + gr) * KHW;
#pragma unroll
            for (int ks = 0; ks < 4; ks++)
                mma_f16(s[nt], qa[ks], kb[ks * 8 + gc], kb[ks * 8 + gc + 4]);
        }
    };

    float o[8][4];
    float lacc[4] = {0.f, 0.f, 0.f, 0.f};
#pragma unroll
    for (int nt = 0; nt < 8; nt++)
#pragma unroll
        for (int j = 0; j < 4; j++) o[nt][j] = 0.f;

    // softmax + PV for tile `it`, consuming s (S(it)) in place
    auto softmaxPV = [&](int it) {
        const int k0 = it * 64;
        {
            const __nv_bfloat16* rh0 = RHb + (wrow + gr) * RLS;
            const __nv_bfloat16* rw0 = RWb + (wrow + gr) * RLS;
            const __nv_bfloat16* rh1 = rh0 + 8 * RLS;
            const __nv_bfloat16* rw1 = rw0 + 8 * RLS;
            int c0 = k0 + 2 * gc;
            int kh0 = c0 / GRID_H;
            int kw0 = c0 - kh0 * GRID_H;    // even: pair never wraps
#pragma unroll
            for (int nt = 0; nt < 8; nt++) {
                float rhv0 = __bfloat162float(rh0[kh0]);
                float rhv1 = __bfloat162float(rh1[kh0]);
                float2 rwv0 = __bfloat1622float2(*(const __nv_bfloat162*)(rw0 + kw0));
                float2 rwv1 = __bfloat1622float2(*(const __nv_bfloat162*)(rw1 + kw0));
                s[nt][0] += rhv0 + rwv0.x;
                s[nt][1] += rhv0 + rwv0.y;
                s[nt][2] += rhv1 + rwv1.x;
                s[nt][3] += rhv1 + rwv1.y;
                kw0 += 8;
                if (kw0 >= GRID_H) { kw0 -= GRID_H; kh0++; }
            }
        }

        uint32_t pf[4][4];
#pragma unroll
        for (int ks = 0; ks < 4; ks++) {
            pf[ks][0] = ex2h2(packh2(s[2 * ks][0], s[2 * ks][1]));
            pf[ks][1] = ex2h2(packh2(s[2 * ks][2], s[2 * ks][3]));
            pf[ks][2] = ex2h2(packh2(s[2 * ks + 1][0], s[2 * ks + 1][1]));
            pf[ks][3] = ex2h2(packh2(s[2 * ks + 1][2], s[2 * ks + 1][3]));
        }

#pragma unroll
        for (int ks = 0; ks < 4; ks++)
            mma_f16(lacc, pf[ks], ONES_H2, ONES_H2);

        const uint32_t* Vp = (const uint32_t*)(Vb + (it & 3) * SLOT_H);
#pragma unroll
        for (int nt = 0; nt < 8; nt++) {
            const uint32_t* vb = Vp + (nt * 8 + gr) * KHW;
#pragma unroll
            for (int ks = 0; ks < 4; ks++)
                mma_f16(o[nt], pf[ks], vb[ks * 8 + gc], vb[ks * 8 + gc + 4]);
        }
    };

    // ---- prologue: tiles 0,1 (group A), 2,3 (group B); wait A; S(0)
    issue_nc(0); issue_nc(1); cp_commit();
    issue_nc(2); issue_nc(3); cp_commit();
    CP_WAIT_GROUP(1);
    __syncthreads();
    computeS(0);

    const int NIT = NSEQ / 64;   // 36 (even)
    for (int t = 0; t < NIT; t += 2) {
        // invariant: tiles t..t+3 resident; s = S(t)
        softmaxPV(t);
        computeS(t + 1);
        softmaxPV(t + 1);

        __syncthreads();                 // all warps done with slots t&3,(t+1)&3
        if (t + 4 < NIT) {
            issue_nc(t + 4);
            if (t + 5 < NIT) issue_nc(t + 5);
            cp_commit();
            CP_WAIT_GROUP(1);            // group (t+2,t+3) landed
        } else {
            CP_WAIT_GROUP(0);
        }
        if (t + 2 < NIT) computeS(t + 2);
    }

    // ---- epilogue: l complete per-lane (ones-mma); write g_ao
    const int b = bh / NHEAD, hh = bh % NHEAD;
    const float inv0 = 1.f / lacc[0], inv1 = 1.f / lacc[2];
    float* d0 = g_ao + (size_t)(b * NSEQ + q0 + wrow + gr) * DIMM + hh * HDIM + 2 * gc;
    float* d1 = d0 + (size_t)8 * DIMM;
#pragma unroll
    for (int nt = 0; nt < 8; nt++) {
        *(float2*)(d0 + nt * 8) = make_float2(o[nt][0] * inv0, o[nt][1] * inv0);
        *(float2*)(d1 + nt * 8) = make_float2(o[nt][2] * inv1, o[nt][3] * inv1);
    }
}

// =================================================================
extern "C" void kernel_launch(void* const* d_in, const int* in_sizes, int n_in,
                              void* d_out, int out_size)
{
    const float* x     = (const float*)d_in[0];
    const float* rph   = (const float*)d_in[1];
    const float* rpw   = (const float*)d_in[2];
    const float* qkvw  = (const float*)d_in[3];
    const float* qkvb  = (const float*)d_in[4];
    const float* projw = (const float*)d_in[5];
    const float* projb = (const float*)d_in[6];
    float* out = (float*)d_out;

    cudaFuncSetAttribute(flash_tc,   cudaFuncAttributeMaxDynamicSharedMemorySize, FLASH_SMEM);
    cudaFuncSetAttribute(rel_kernel, cudaFuncAttributeMaxDynamicSharedMemorySize, REL_SMEM);

    // 1) QKV projection + head split (fp16 mma, 3-stage pipeline)
    gemm_tc<0><<<dim3(2304 / 128, MROWS / 128), dim3(256)>>>(x, qkvw, qkvb, nullptr, 2304, DIMM);
    // 2) rel-pos bias tables (log2e-scaled)
    rel_kernel<<<dim3(GRID_H, BHN), dim3(256), REL_SMEM>>>(rph, rpw);
    // 3) fused flash attention (2 key-tiles per barrier region)
    flash_tc<<<dim3(NSEQ / 128, BHN), dim3(256), FLASH_SMEM>>>();
    // 4) output projection (fp16 mma, 3-stage pipeline)
    gemm_tc<1><<<dim3(DIMM / 128, MROWS / 128), dim3(256)>>>(nullptr, projw, projb, out, DIMM, DIMM);
}

// round 17
// speedup vs baseline: 1.0900x; 1.0099x over previous
#include <cuda_runtime.h>
#include <cuda_fp16.h>
#include <cuda_bf16.h>
#include <math.h>
#include <stdint.h>

// Problem constants
#define DIMM   768
#define NHEAD  12
#define HDIM   64
#define BATCH  2
#define GRID_H 48
#define NSEQ   2304          // 48*48
#define BHN    24            // BATCH*NHEAD
#define MROWS  4608          // BATCH*NSEQ
#define SCALE  0.125f        // 64^-0.5
#define LOG2E  1.44269504088896f

// ---------------- device scratch (static: no cudaMalloc allowed) ----------------
__device__ float  g_q [BHN * NSEQ * HDIM];      // [bh][n][c], unscaled fp32
__device__ __half g_kh[BHN * NSEQ * HDIM];      // [bh][n][c] fp16
__device__ __half g_vh[BHN * NSEQ * HDIM];      // [bh][n][c] fp16 (row-major)
__device__ float  g_relh[BHN * NSEQ * GRID_H];  // [bh][q][kh] (pre-scaled by log2e)
__device__ float  g_relw[BHN * NSEQ * GRID_H];  // [bh][q][kw] (pre-scaled by log2e)
__device__ float  g_ao[MROWS * DIMM];           // attention output (b,n,dim)

// ---------------- helpers ----------------
__device__ __forceinline__ uint32_t packh2(float a, float b) {
    __half2 h = __floats2half2_rn(a, b);
    return *(uint32_t*)&h;
}
__device__ __forceinline__ uint32_t ex2h2(uint32_t x) {
    uint32_t r;
    asm("ex2.approx.f16x2 %0, %1;" : "=r"(r) : "r"(x));
    return r;
}

// D(16x8,f32) += A(16x16,f16,row) * B(16x8,f16,col)
__device__ __forceinline__ void mma_f16(float* d, const uint32_t* a,
                                        uint32_t b0, uint32_t b1) {
    asm volatile(
        "mma.sync.aligned.m16n8k16.row.col.f32.f16.f16.f32 "
        "{%0,%1,%2,%3}, {%4,%5,%6,%7}, {%8,%9}, {%0,%1,%2,%3};"
        : "+f"(d[0]), "+f"(d[1]), "+f"(d[2]), "+f"(d[3])
        : "r"(a[0]), "r"(a[1]), "r"(a[2]), "r"(a[3]), "r"(b0), "r"(b1));
}

__device__ __forceinline__ void ldsm_x4(uint32_t* r, uint32_t addr) {
    asm volatile("ldmatrix.sync.aligned.m8n8.x4.shared.b16 {%0,%1,%2,%3}, [%4];"
        : "=r"(r[0]), "=r"(r[1]), "=r"(r[2]), "=r"(r[3]) : "r"(addr));
}
__device__ __forceinline__ void ldsm_x4_t(uint32_t* r, uint32_t addr) {
    asm volatile("ldmatrix.sync.aligned.m8n8.x4.trans.shared.b16 {%0,%1,%2,%3}, [%4];"
        : "=r"(r[0]), "=r"(r[1]), "=r"(r[2]), "=r"(r[3]) : "r"(addr));
}

__device__ __forceinline__ void cp_async16(void* smem_dst, const void* gmem_src) {
    uint32_t s = (uint32_t)__cvta_generic_to_shared(smem_dst);
    asm volatile("cp.async.cg.shared.global [%0], [%1], 16;\n" :: "r"(s), "l"(gmem_src));
}
__device__ __forceinline__ void cp_commit() { asm volatile("cp.async.commit_group;\n"); }
#define CP_WAIT_GROUP(n) asm volatile("cp.async.wait_group %0;\n" :: "n"(n))

// =================================================================
// fp16 tensor-core GEMM NT, cp.async 3-stage pipeline (R11 proven).
// MODE 0: q -> g_q fp32, k -> g_kh fp16, v -> g_vh fp16 (row-major,
// coalesced — no transpose scatter). MODE 1: A=g_ao, fp32 out.
// =================================================================
#define GPAD 24

template<int MODE>
__global__ __launch_bounds__(256, 2) void gemm_tc(const float* __restrict__ Aext,
                                                  const float* __restrict__ B,
                                                  const float* __restrict__ bias,
                                                  float* __restrict__ Cout,
                                                  int Ncol, int K)
{
    __shared__ float As[3][128][GPAD];
    __shared__ float Bs[3][128][GPAD];
    const float* A = (MODE == 0) ? Aext : (const float*)g_ao;

    const int m0 = blockIdx.y * 128;
    const int n0 = blockIdx.x * 128;
    const int tid = threadIdx.x;
    const int lane = tid & 31;
    const int wid = tid >> 5;
    const int wm = (wid & 1) * 64;
    const int wn = (wid >> 1) * 32;
    const int gr = lane >> 2;
    const int gc = lane & 3;
    const int sr = tid >> 2;
    const int sc = (tid & 3) << 2;

    float acc[4][4][4];
#pragma unroll
    for (int mi = 0; mi < 4; mi++)
#pragma unroll
        for (int ni = 0; ni < 4; ni++)
#pragma unroll
            for (int j = 0; j < 4; j++) acc[mi][ni][j] = 0.f;

    auto issue = [&](int k0, int pb) {
        cp_async16(&As[pb][sr][sc],      A + (size_t)(m0 + sr) * K + k0 + sc);
        cp_async16(&As[pb][sr + 64][sc], A + (size_t)(m0 + sr + 64) * K + k0 + sc);
        cp_async16(&Bs[pb][sr][sc],      B + (size_t)(n0 + sr) * K + k0 + sc);
        cp_async16(&Bs[pb][sr + 64][sc], B + (size_t)(n0 + sr + 64) * K + k0 + sc);
        cp_commit();
    };

    issue(0, 0);
    issue(16, 1);

    const int nk = K / 16;
    int p = 0;
    for (int kt = 0; kt < nk; kt++) {
        CP_WAIT_GROUP(1);
        __syncthreads();
        if (kt + 2 < nk) issue((kt + 2) * 16, (p + 2 >= 3) ? p - 1 : p + 2);

        uint32_t af[4][4], bf[4][2];
#pragma unroll
        for (int mi = 0; mi < 4; mi++) {
            const float* ap0 = &As[p][wm + mi * 16 + gr][2 * gc];
            const float* ap1 = ap0 + 8 * GPAD;
            float2 x0 = *(const float2*)ap0;
            float2 x1 = *(const float2*)ap1;
            float2 x2 = *(const float2*)(ap0 + 8);
            float2 x3 = *(const float2*)(ap1 + 8);
            af[mi][0] = packh2(x0.x, x0.y);
            af[mi][1] = packh2(x1.x, x1.y);
            af[mi][2] = packh2(x2.x, x2.y);
            af[mi][3] = packh2(x3.x, x3.y);
        }
#pragma unroll
        for (int ni = 0; ni < 4; ni++) {
            const float* bp = &Bs[p][wn + ni * 8 + gr][2 * gc];
            float2 y0 = *(const float2*)bp;
            float2 y1 = *(const float2*)(bp + 8);
            bf[ni][0] = packh2(y0.x, y0.y);
            bf[ni][1] = packh2(y1.x, y1.y);
        }
#pragma unroll
        for (int mi = 0; mi < 4; mi++)
#pragma unroll
            for (int ni = 0; ni < 4; ni++)
                mma_f16(acc[mi][ni], af[mi], bf[ni][0], bf[ni][1]);

        p = (p + 1 >= 3) ? 0 : p + 1;
    }

    // ---- epilogue
#pragma unroll
    for (int ni = 0; ni < 4; ni++) {
        const int nb = n0 + wn + ni * 8 + 2 * gc;
        const float bbx = bias[nb], bby = bias[nb + 1];
        if (MODE == 0) {
            const int part = nb / DIMM;
            const int hh = (nb % DIMM) / HDIM;
            const int cb = nb % HDIM;
#pragma unroll
            for (int mi = 0; mi < 4; mi++) {
                int m = m0 + wm + mi * 16 + gr;
                int b = m / NSEQ, nn = m % NSEQ;
                int bh = b * NHEAD + hh;
                float v0 = acc[mi][ni][0] + bbx, v1 = acc[mi][ni][1] + bby;
                float v2 = acc[mi][ni][2] + bbx, v3 = acc[mi][ni][3] + bby;
                if (part == 0) {
                    float* d0 = g_q + (size_t)(bh * NSEQ + nn) * HDIM + cb;
                    *(float2*)d0 = make_float2(v0, v1);
                    *(float2*)(d0 + 8 * HDIM) = make_float2(v2, v3);
                } else {
                    __half* dst = (part == 1) ? g_kh : g_vh;
                    __half* d0 = dst + (size_t)(bh * NSEQ + nn) * HDIM + cb;
                    *(__half2*)d0 = __floats2half2_rn(v0, v1);
                    *(__half2*)(d0 + 8 * HDIM) = __floats2half2_rn(v2, v3);
                }
            }
        } else {
#pragma unroll
            for (int mi = 0; mi < 4; mi++) {
                int m = m0 + wm + mi * 16 + gr;
                *(float2*)(Cout + (size_t)m * Ncol + nb) =
                    make_float2(acc[mi][ni][0] + bbx, acc[mi][ni][1] + bby);
                *(float2*)(Cout + (size_t)(m + 8) * Ncol + nb) =
                    make_float2(acc[mi][ni][2] + bbx, acc[mi][ni][3] + bby);
            }
        }
    }
}

// =================================================================
// rel bias tables — outputs pre-multiplied by log2(e)
// =================================================================
#define REL_SMEM ((3072 + 3072 + 6080) * 4)

__global__ __launch_bounds__(256) void rel_kernel(const float* __restrict__ rph,
                                                  const float* __restrict__ rpw)
{
    extern __shared__ float sm[];
    float* qs = sm;            // [48][64]
    float* rh = sm + 3072;     // [48][64]
    float* rw = sm + 6144;     // [95][64]

    const int qh = blockIdx.x;
    const int bh = blockIdx.y;
    const int tid = threadIdx.x;

    const float4* qsrc = (const float4*)(g_q + (size_t)(bh * NSEQ + qh * GRID_H) * HDIM);
#pragma unroll
    for (int i = 0; i < 3; i++) ((float4*)qs)[tid + i * 256] = qsrc[tid + i * 256];

    for (int i = tid; i < 768; i += 256) {
        int kh = i >> 4, cc = i & 15;
        ((float4*)rh)[i] = ((const float4*)(rph + (size_t)(qh - kh + 47) * HDIM))[cc];
    }
    for (int i = tid; i < 1520; i += 256) ((float4*)rw)[i] = ((const float4*)rpw)[i];
    __syncthreads();

    for (int idx = tid; idx < 2304; idx += 256) {
        int qw = idx / GRID_H;
        int kk = idx - qw * GRID_H;
        const float4* qp = (const float4*)(qs + qw * HDIM);
        const float4* hp = (const float4*)(rh + kk * HDIM);
        const float4* wp = (const float4*)(rw + (qw - kk + 47) * HDIM);
        float sh = 0.f, sw2 = 0.f;
#pragma unroll
        for (int c = 0; c < 16; c++) {
            float4 a = qp[c], hb = hp[c], wb = wp[c];
            sh  += a.x * hb.x + a.y * hb.y + a.z * hb.z + a.w * hb.w;
            sw2 += a.x * wb.x + a.y * wb.y + a.z * wb.z + a.w * wb.w;
        }
        size_t base = ((size_t)bh * NSEQ + (size_t)qh * GRID_H + qw) * GRID_H + kk;
        g_relh[base] = sh * LOG2E;
        g_relw[base] = sw2 * LOG2E;
    }
}

// =================================================================
// Flash attention (R15 structure): fp16 mma, f16x2 exp, l-via-ones-
// mma, 128-q tile, 8 warps, 4-slot ring, 2 key-tiles per barrier
// region — fragment loads via ldmatrix (K: x4 non-trans; V: x4.trans
// on row-major V). Second K ldsm at +64B (ch 32..63), NOT +128 (R16 bug).
// =================================================================
#define KHS 72                 // fp16 row stride (144 B)
#define RLS 52
#define SLOT_H (64 * KHS)      // fp16 elems per slot
#define FLASH_SMEM (8 * SLOT_H * 2 + 2 * 128 * RLS * 2)
#define ONES_H2 0x3C003C00u    // half2(1.0, 1.0)

__global__ __launch_bounds__(256, 2) void flash_tc()
{
    extern __shared__ char smraw[];
    __half* Kb = (__half*)smraw;                          // [4][64][72]
    __half* Vb = Kb + 4 * SLOT_H;                         // [4][64][72] row-major
    __nv_bfloat16* RHb = (__nv_bfloat16*)(Vb + 4 * SLOT_H);
    __nv_bfloat16* RWb = RHb + 128 * RLS;

    const int bh = blockIdx.y;
    const int q0 = blockIdx.x * 128;
    const int tid = threadIdx.x;
    const int lane = tid & 31;
    const int wid = tid >> 5;
    const int wrow = wid * 16;
    const int gr = lane >> 2;
    const int gc = lane & 3;

    const float* qg = g_q + (size_t)bh * NSEQ * HDIM;
    const __half* kg = g_kh + (size_t)bh * NSEQ * HDIM;
    const __half* vg = g_vh + (size_t)bh * NSEQ * HDIM;

    const uint32_t kb_u32 = (uint32_t)__cvta_generic_to_shared(Kb);
    const uint32_t vb_u32 = (uint32_t)__cvta_generic_to_shared(Vb);

    const int ldrow = tid >> 2;          // 0..63
    const int ldc0 = (tid & 3) * 16;     // fp16 col slice base

    // issue one tile's K/V (NO commit — caller groups tiles)
    auto issue_nc = [&](int tile) {
        const __half* ksrc = kg + (size_t)(tile * 64 + ldrow) * HDIM + ldc0;
        const __half* vsrc = vg + (size_t)(tile * 64 + ldrow) * HDIM + ldc0;
        __half* kd = Kb + (tile & 3) * SLOT_H + ldrow * KHS + ldc0;
        __half* vd = Vb + (tile & 3) * SLOT_H + ldrow * KHS + ldc0;
        cp_async16(kd, ksrc);
        cp_async16(kd + 8, ksrc + 8);
        cp_async16(vd, vsrc);
        cp_async16(vd + 8, vsrc + 8);
    };

    // ---- Q fragments (fp16, scaled by SCALE*log2e)
    uint32_t qa[4][4];
    {
        const float qsc = SCALE * LOG2E;
        const float* qr0 = qg + (size_t)(q0 + wrow + gr) * HDIM;
        const float* qr1 = qr0 + 8 * HDIM;
#pragma unroll
        for (int ks = 0; ks < 4; ks++) {
            int c = ks * 16 + 2 * gc;
            qa[ks][0] = packh2(qr0[c] * qsc, qr0[c + 1] * qsc);
            qa[ks][1] = packh2(qr1[c] * qsc, qr1[c + 1] * qsc);
            qa[ks][2] = packh2(qr0[c + 8] * qsc, qr0[c + 9] * qsc);
            qa[ks][3] = packh2(qr1[c + 8] * qsc, qr1[c + 9] * qsc);
        }
    }

    // ---- rel bias slices -> bf16 SMEM [128][48] (stride 52)
    {
        const float4* srcH = (const float4*)(g_relh + ((size_t)bh * NSEQ + q0) * GRID_H);
        const float4* srcW = (const float4*)(g_relw + ((size_t)bh * NSEQ + q0) * GRID_H);
        for (int i = tid; i < 1536; i += 256) {
            int r = i / 12, c4 = i % 12;
            float4 vh = srcH[i], vw = srcW[i];
            __nv_bfloat162* dh = (__nv_bfloat162*)(RHb + r * RLS + c4 * 4);
            __nv_bfloat162* dw = (__nv_bfloat162*)(RWb + r * RLS + c4 * 4);
            dh[0] = __floats2bfloat162_rn(vh.x, vh.y);
            dh[1] = __floats2bfloat162_rn(vh.z, vh.w);
            dw[0] = __floats2bfloat162_rn(vw.x, vw.y);
            dw[1] = __floats2bfloat162_rn(vw.z, vw.w);
        }
    }

    // S-tile via ldmatrix: per nt, 2x ldmatrix.x4 cover ch 0..31 / 32..63
    float s[8][4];
    auto computeS = [&](int tile) {
        const uint32_t Kp = kb_u32 + (uint32_t)((tile & 3) * SLOT_H * 2);
        const uint32_t arow = (uint32_t)((lane & 7) * (KHS * 2) + (lane >> 3) * 16);
#pragma unroll
        for (int nt = 0; nt < 8; nt++) {
            uint32_t a0 = Kp + (uint32_t)(nt * 8 * (KHS * 2)) + arow;
            uint32_t kf[8];
            ldsm_x4(kf, a0);
            ldsm_x4(kf + 4, a0 + 64);   // channels 32..63 (bytes 64..127)
            s[nt][0] = s[nt][1] = s[nt][2] = s[nt][3] = 0.f;
            mma_f16(s[nt], qa[0], kf[0], kf[1]);
            mma_f16(s[nt], qa[1], kf[2], kf[3]);
            mma_f16(s[nt], qa[2], kf[4], kf[5]);
            mma_f16(s[nt], qa[3], kf[6], kf[7]);
        }
    };

    float o[8][4];
    float lacc[4] = {0.f, 0.f, 0.f, 0.f};
#pragma unroll
    for (int nt = 0; nt < 8; nt++)
#pragma unroll
        for (int j = 0; j < 4; j++) o[nt][j] = 0.f;

    // softmax + PV for tile `it`, consuming s (S(it)) in place
    auto softmaxPV = [&](int it) {
        const int k0 = it * 64;
        {
            const __nv_bfloat16* rh0 = RHb + (wrow + gr) * RLS;
            const __nv_bfloat16* rw0 = RWb + (wrow + gr) * RLS;
            const __nv_bfloat16* rh1 = rh0 + 8 * RLS;
            const __nv_bfloat16* rw1 = rw0 + 8 * RLS;
            int c0 = k0 + 2 * gc;
            int kh0 = c0 / GRID_H;
            int kw0 = c0 - kh0 * GRID_H;    // even: pair never wraps
#pragma unroll
            for (int nt = 0; nt < 8; nt++) {
                float rhv0 = __bfloat162float(rh0[kh0]);
                float rhv1 = __bfloat162float(rh1[kh0]);
                float2 rwv0 = __bfloat1622float2(*(const __nv_bfloat162*)(rw0 + kw0));
                float2 rwv1 = __bfloat1622float2(*(const __nv_bfloat162*)(rw1 + kw0));
                s[nt][0] += rhv0 + rwv0.x;
                s[nt][1] += rhv0 + rwv0.y;
                s[nt][2] += rhv1 + rwv1.x;
                s[nt][3] += rhv1 + rwv1.y;
                kw0 += 8;
                if (kw0 >= GRID_H) { kw0 -= GRID_H; kh0++; }
            }
        }

        uint32_t pf[4][4];
#pragma unroll
        for (int ks = 0; ks < 4; ks++) {
            pf[ks][0] = ex2h2(packh2(s[2 * ks][0], s[2 * ks][1]));
            pf[ks][1] = ex2h2(packh2(s[2 * ks][2], s[2 * ks][3]));
            pf[ks][2] = ex2h2(packh2(s[2 * ks + 1][0], s[2 * ks + 1][1]));
            pf[ks][3] = ex2h2(packh2(s[2 * ks + 1][2], s[2 * ks + 1][3]));
        }

#pragma unroll
        for (int ks = 0; ks < 4; ks++)
            mma_f16(lacc, pf[ks], ONES_H2, ONES_H2);

        // PV: V B-frags via ldmatrix.trans on row-major V.
        // First x4: keys 0-31 (rows lane), col octet nt; second: keys 32-63.
        const uint32_t Vp = vb_u32 + (uint32_t)((it & 3) * SLOT_H * 2);
        const uint32_t aV = Vp + (uint32_t)(lane * (KHS * 2));
#pragma unroll
        for (int nt = 0; nt < 8; nt++) {
            uint32_t vf[8];
            ldsm_x4_t(vf, aV + nt * 16);
            ldsm_x4_t(vf + 4, aV + nt * 16 + 32 * (KHS * 2));
            mma_f16(o[nt], pf[0], vf[0], vf[1]);
            mma_f16(o[nt], pf[1], vf[2], vf[3]);
            mma_f16(o[nt], pf[2], vf[4], vf[5]);
            mma_f16(o[nt], pf[3], vf[6], vf[7]);
        }
    };

    // ---- prologue: tiles 0,1 (group A), 2,3 (group B); wait A; S(0)
    issue_nc(0); issue_nc(1); cp_commit();
    issue_nc(2); issue_nc(3); cp_commit();
    CP_WAIT_GROUP(1);
    __syncthreads();
    computeS(0);

    const int NIT = NSEQ / 64;   // 36 (even)
    for (int t = 0; t < NIT; t += 2) {
        // invariant: tiles t..t+3 resident; s = S(t)
        softmaxPV(t);
        computeS(t + 1);
        softmaxPV(t + 1);

        __syncthreads();                 // all warps done with slots t&3,(t+1)&3
        if (t + 4 < NIT) {
            issue_nc(t + 4);
            if (t + 5 < NIT) issue_nc(t + 5);
            cp_commit();
            CP_WAIT_GROUP(1);            // group (t+2,t+3) landed
        } else {
            CP_WAIT_GROUP(0);
        }
        if (t + 2 < NIT) computeS(t + 2);
    }

    // ---- epilogue: l complete per-lane (ones-mma); write g_ao
    const int b = bh / NHEAD, hh = bh % NHEAD;
    const float inv0 = 1.f / lacc[0], inv1 = 1.f / lacc[2];
    float* d0 = g_ao + (size_t)(b * NSEQ + q0 + wrow + gr) * DIMM + hh * HDIM + 2 * gc;
    float* d1 = d0 + (size_t)8 * DIMM;
#pragma unroll
    for (int nt = 0; nt < 8; nt++) {
        *(float2*)(d0 + nt * 8) = make_float2(o[nt][0] * inv0, o[nt][1] * inv0);
        *(float2*)(d1 + nt * 8) = make_float2(o[nt][2] * inv1, o[nt][3] * inv1);
    }
}

// =================================================================
extern "C" void kernel_launch(void* const* d_in, const int* in_sizes, int n_in,
                              void* d_out, int out_size)
{
    const float* x     = (const float*)d_in[0];
    const float* rph   = (const float*)d_in[1];
    const float* rpw   = (const float*)d_in[2];
    const float* qkvw  = (const float*)d_in[3];
    const float* qkvb  = (const float*)d_in[4];
    const float* projw = (const float*)d_in[5];
    const float* projb = (const float*)d_in[6];
    float* out = (float*)d_out;

    cudaFuncSetAttribute(flash_tc,   cudaFuncAttributeMaxDynamicSharedMemorySize, FLASH_SMEM);
    cudaFuncSetAttribute(rel_kernel, cudaFuncAttributeMaxDynamicSharedMemorySize, REL_SMEM);

    // 1) QKV projection + head split (fp16 mma; V row-major, coalesced)
    gemm_tc<0><<<dim3(2304 / 128, MROWS / 128), dim3(256)>>>(x, qkvw, qkvb, nullptr, 2304, DIMM);
    // 2) rel-pos bias tables (log2e-scaled)
    rel_kernel<<<dim3(GRID_H, BHN), dim3(256), REL_SMEM>>>(rph, rpw);
    // 3) fused flash attention (ldmatrix fragment loads, fixed offsets)
    flash_tc<<<dim3(NSEQ / 128, BHN), dim3(256), FLASH_SMEM>>>();
    // 4) output projection (fp16 mma, 3-stage pipeline)
    gemm_tc<1><<<dim3(DIMM / 128, MROWS / 128), dim3(256)>>>(nullptr, projw, projb, out, DIMM, DIMM);
}